// round 15
// baseline (speedup 1.0000x reference)
#include <cuda_runtime.h>
#include <cuda_fp16.h>
#include <math.h>

#define BB 4
#define CC 512
#define TT 1024
#define HH 8
#define HDD 64
#define FF 2048
#define LL 4
#define WW 4
#define RNUM 9

// ---------------- scratch (no allocations allowed) ----------------
__device__ float g_x[BB*CC*TT];          // fp32 residual / layer state
__device__ float g_t[BB*CC*TT];          // fp32 gemm output (pre-LN)
// fp16 activations
__device__ __half g_xf[BB*CC*TT];
__device__ __half g_qkv[BB*3*CC*TT];     // fused q|k|v per batch
__device__ __half g_of[BB*CC*TT];
__device__ __half g_hf[BB*FF*TT];
// fp16 weights
__device__ __half g_wqkv[LL*3*CC*CC];    // [L][q|k|v][CC][CC]
__device__ float  g_bqkv[LL*3*CC];
__device__ __half g_wo[LL*CC*CC];
__device__ __half g_w1[LL*FF*CC], g_w2[LL*CC*FF];

// ---------------- helpers ----------------
__device__ __forceinline__ void mma16816(float* d, const unsigned* a, const unsigned* b){
    asm volatile("mma.sync.aligned.m16n8k16.row.col.f32.f16.f16.f32 "
        "{%0,%1,%2,%3}, {%4,%5,%6,%7}, {%8,%9}, {%0,%1,%2,%3};"
        : "+f"(d[0]),"+f"(d[1]),"+f"(d[2]),"+f"(d[3])
        : "r"(a[0]),"r"(a[1]),"r"(a[2]),"r"(a[3]), "r"(b[0]),"r"(b[1]));
}
__device__ __forceinline__ void ldsm4(unsigned* r, const void* p){
    unsigned addr = (unsigned)__cvta_generic_to_shared(p);
    asm volatile("ldmatrix.sync.aligned.m8n8.x4.shared.b16 {%0,%1,%2,%3}, [%4];"
        : "=r"(r[0]),"=r"(r[1]),"=r"(r[2]),"=r"(r[3]) : "r"(addr));
}
__device__ __forceinline__ void ldsm4t(unsigned* r, const void* p){
    unsigned addr = (unsigned)__cvta_generic_to_shared(p);
    asm volatile("ldmatrix.sync.aligned.m8n8.x4.trans.shared.b16 {%0,%1,%2,%3}, [%4];"
        : "=r"(r[0]),"=r"(r[1]),"=r"(r[2]),"=r"(r[3]) : "r"(addr));
}
__device__ __forceinline__ unsigned pack_h2(float x, float y){
    __half2 t = __floats2half2_rn(x, y);
    return *(unsigned*)&t;
}
__device__ __forceinline__ void cpa16(void* s, const void* g){
    unsigned sa = (unsigned)__cvta_generic_to_shared(s);
    asm volatile("cp.async.cg.shared.global [%0], [%1], 16;" :: "r"(sa), "l"(g));
}
__device__ __forceinline__ void cpcommit(){ asm volatile("cp.async.commit_group;"); }
template<int NN> __device__ __forceinline__ void cpwait(){ asm volatile("cp.async.wait_group %0;" :: "n"(NN)); }

// ---------------- prologue converts ----------------
__global__ void cvt_copy_kernel(const float* __restrict__ in, float* __restrict__ of,
                                __half* __restrict__ o, int n){
    int i = (blockIdx.x*blockDim.x + threadIdx.x)*4;
    if (i >= n) return;
    float4 v = *(const float4*)&in[i];
    *(float4*)&of[i] = v;
    *(__half2*)&o[i]   = __floats2half2_rn(v.x, v.y);
    *(__half2*)&o[i+2] = __floats2half2_rn(v.z, v.w);
}
// interleave q,k,v weights -> [L][3][CC][CC]
__global__ void cvt3_kernel(const float* __restrict__ q, const float* __restrict__ k,
                            const float* __restrict__ v, __half* __restrict__ dst){
    const int per = CC*CC;
    int i = (blockIdx.x*blockDim.x + threadIdx.x)*4;
    if (i >= LL*3*per) return;
    int layer = i/(3*per); int rem = i - layer*3*per; int sel = rem/per; int off = rem - sel*per;
    const float* s = sel==0 ? q : (sel==1 ? k : v);
    float4 vv = *(const float4*)&s[layer*per + off];
    *(__half2*)&dst[i]   = __floats2half2_rn(vv.x, vv.y);
    *(__half2*)&dst[i+2] = __floats2half2_rn(vv.z, vv.w);
}
__global__ void cat_bias_kernel(const float* __restrict__ qb, const float* __restrict__ kb,
                                const float* __restrict__ vb, float* __restrict__ dst){
    int i = blockIdx.x*blockDim.x + threadIdx.x;
    if (i >= LL*3*CC) return;
    int layer = i/(3*CC); int rem = i - layer*3*CC; int sel = rem/CC; int off = rem - sel*CC;
    const float* s = sel==0 ? qb : (sel==1 ? kb : vb);
    dst[i] = s[layer*CC + off];
}
// fused convert of ow, w1, w2
#define NW_O  (LL*CC*CC)
#define NW_F  (LL*FF*CC)
__global__ void cvt_w_kernel(const float* __restrict__ ow, const float* __restrict__ w1,
                             const float* __restrict__ w2,
                             __half* __restrict__ dow, __half* __restrict__ dw1,
                             __half* __restrict__ dw2){
    int i = (blockIdx.x*blockDim.x + threadIdx.x)*4;
    const float* s; __half* d; int off;
    if (i < NW_O){ s = ow; d = dow; off = i; }
    else if (i < NW_O + NW_F){ s = w1; d = dw1; off = i - NW_O; }
    else if (i < NW_O + 2*NW_F){ s = w2; d = dw2; off = i - NW_O - NW_F; }
    else return;
    float4 v = *(const float4*)&s[off];
    *(__half2*)&d[off]   = __floats2half2_rn(v.x, v.y);
    *(__half2*)&d[off+2] = __floats2half2_rn(v.z, v.w);
}

// ---------------- fp16 GEMM, 64-k double-buffered cp.async stages ----------------
// out[b][m][n] = sum_k A[m][k] B[b][k][n] (+bias, epilogue). rows<scaleM get *scale.
#define GA_ELEMS (128*72)
#define GB_ELEMS (64*136)
#define GEMM_SMEM_BYTES (2*(GA_ELEMS + GB_ELEMS)*2)
template<int RELU, int MASK_OUT, int F16_OUT, int DO_SCALE>
__global__ void __launch_bounds__(256,2) gemm_f16_kernel(
    const __half* __restrict__ A_g, const __half* __restrict__ B_g,
    const float* __restrict__ bias, const float* __restrict__ mask,
    float* __restrict__ outF, __half* __restrict__ outH,
    int M, int N, int K, float scale, int scaleM)
{
    extern __shared__ char gsm[];
    __half* Asm = (__half*)gsm;                       // [2][128][72]
    __half* Bsm = (__half*)gsm + 2*GA_ELEMS;          // [2][64][136]

    int b = blockIdx.z;
    const __half* B_b = B_g + (size_t)b*K*N;
    int m0 = blockIdx.y*128, n0 = blockIdx.x*128;
    int tid = threadIdx.x;
    int l = tid & 31, w = tid >> 5;
    int wm0 = (w >> 2) * 64;
    int wn0 = (w & 3) * 32;

    float acc[4][4][4];
    #pragma unroll
    for (int mi=0;mi<4;mi++)
        #pragma unroll
        for (int ni=0;ni<4;ni++)
            #pragma unroll
            for (int e=0;e<4;e++) acc[mi][ni][e]=0.f;

    int nt = K/64;
    auto load_stage = [&](int it, int buf){
        int k0 = it*64;
        __half* As = Asm + buf*GA_ELEMS;
        __half* Bs = Bsm + buf*GB_ELEMS;
        #pragma unroll
        for (int p=0;p<4;p++){
            int c = tid + p*256;
            int row = c>>3, col8 = (c&7)*8;
            cpa16(&As[row*72 + col8], A_g + (size_t)(m0+row)*K + k0 + col8);
        }
        #pragma unroll
        for (int p=0;p<4;p++){
            int c = tid + p*256;
            int row = c>>4, col8 = (c&15)*8;
            cpa16(&Bs[row*136 + col8], B_b + (size_t)(k0+row)*N + n0 + col8);
        }
    };

    load_stage(0,0); cpcommit();
    if (nt > 1){ load_stage(1,1); cpcommit(); }

    for (int it=0; it<nt; ++it){
        int buf = it & 1;
        if (it+1 < nt) cpwait<1>(); else cpwait<0>();
        __syncthreads();

        const __half* As = Asm + buf*GA_ELEMS;
        const __half* Bs = Bsm + buf*GB_ELEMS;

        #pragma unroll
        for (int ks=0; ks<64; ks+=16){
            unsigned Bq[2][4];
            #pragma unroll
            for (int nip=0;nip<2;nip++){
                int row = ks + ((l>>3)&1)*8 + (l&7);
                int col = wn0 + nip*16 + ((l>>4)&1)*8;
                ldsm4t(Bq[nip], &Bs[row*136 + col]);
            }
            #pragma unroll
            for (int mi=0;mi<4;mi++){
                unsigned Af[4];
                ldsm4(Af, &As[(wm0 + mi*16 + (l & 15))*72 + ks + (l >> 4)*8]);
                #pragma unroll
                for (int nip=0;nip<2;nip++){
                    mma16816(acc[mi][2*nip],   Af, &Bq[nip][0]);
                    mma16816(acc[mi][2*nip+1], Af, &Bq[nip][2]);
                }
            }
        }
        __syncthreads();
        if (it+2 < nt){ load_stage(it+2, buf); cpcommit(); }
    }

    // epilogue
    float tsc = (DO_SCALE && m0 < scaleM) ? scale : 1.f;
    #pragma unroll
    for (int mi=0;mi<4;mi++){
        int r = m0 + wm0 + mi*16 + (l >> 2);
        float bv0 = bias[r], bv1 = bias[r+8];
        #pragma unroll
        for (int ni=0;ni<4;ni++){
            int cn = n0 + wn0 + ni*8 + (l & 3)*2;
            float m00=1.f, m01=1.f;
            if (MASK_OUT){
                m00 = mask[(size_t)b*TT + cn];
                m01 = mask[(size_t)b*TT + cn + 1];
            }
            float c0 = acc[mi][ni][0] + bv0;
            float c1 = acc[mi][ni][1] + bv0;
            float c2 = acc[mi][ni][2] + bv1;
            float c3 = acc[mi][ni][3] + bv1;
            if (DO_SCALE){ c0*=tsc; c1*=tsc; c2*=tsc; c3*=tsc; }
            if (RELU){ c0=fmaxf(c0,0.f); c1=fmaxf(c1,0.f); c2=fmaxf(c2,0.f); c3=fmaxf(c3,0.f); }
            if (MASK_OUT){ c0*=m00; c1*=m01; c2*=m00; c3*=m01; }
            size_t base = (size_t)b*M*N;
            if (F16_OUT){
                *(__half2*)&outH[base + (size_t)r*N + cn]     = __floats2half2_rn(c0,c1);
                *(__half2*)&outH[base + (size_t)(r+8)*N + cn] = __floats2half2_rn(c2,c3);
            } else {
                *(float2*)&outF[base + (size_t)r*N + cn]     = make_float2(c0,c1);
                *(float2*)&outF[base + (size_t)(r+8)*N + cn] = make_float2(c2,c3);
            }
        }
    }
}

// ---------------- tensor-core flash attention, fp16, double-buffered K/V ----------------
// grid (T/64, H, B), 128 threads (4 warps), 4 CTAs/SM (single wave on 148 SMs).
#define KQS 72
#define NJT (TT/64)
__global__ void __launch_bounds__(128,4) attn_mma_kernel(
    const __half* __restrict__ qkv,
    const float* __restrict__ relk, const float* __restrict__ relv,
    const float* __restrict__ mask, __half* __restrict__ of)
{
    extern __shared__ char smraw[];
    __half* Qf = (__half*)smraw;                      // [64 d][72]
    __half* Kf = Qf + 64*KQS;                         // [2][64 d][72]
    __half* Vf = Kf + 2*64*KQS;                       // [2][64 d][72]
    float* sQRK  = (float*)(Vf + 2*64*KQS);           // [64 i][9]
    float* sRK   = sQRK + 64*RNUM;                    // [9][64]
    float* sRV   = sRK + RNUM*64;                     // [9][64]
    float* sPB   = sRV + RNUM*64;                     // [64 i][12]
    float* sMask = sPB + 64*12;                       // [2][64]
    float* sO    = (float*)Kf;                        // [64 d][68] fp32 out stage (overlays K)

    int tid = threadIdx.x;
    int l = tid & 31, w = tid >> 5;
    int r = l >> 2;
    int c2 = (l & 3) * 2;
    int i0 = blockIdx.x * 64;
    int h  = blockIdx.y;
    int b  = blockIdx.z;
    const size_t hbq = ((size_t)b*3*CC + h*HDD) * TT;
    const size_t hbk = hbq + (size_t)CC*TT;
    const size_t hbv = hbq + (size_t)2*CC*TT;
    const size_t hbo = ((size_t)b*CC + h*HDD) * TT;

    auto load_kv = [&](int jt, int buf){
        int j0t = jt*64;
        #pragma unroll
        for (int p=0;p<4;p++){
            int c = tid + p*128;
            int row = c>>3, col8 = (c&7)*8;
            size_t go = (size_t)row*TT + j0t + col8;
            cpa16(&Kf[buf*64*KQS + row*KQS + col8], qkv + hbk + go);
            cpa16(&Vf[buf*64*KQS + row*KQS + col8], qkv + hbv + go);
        }
    };

    // Q tile
    #pragma unroll
    for (int p=0;p<4;p++){
        int c = tid + p*128;
        int row = c>>3, col8 = (c&7)*8;
        cpa16(&Qf[row*KQS + col8], qkv + hbq + (size_t)row*TT + i0 + col8);
    }
    cpcommit();
    load_kv(0,0); cpcommit();
    for (int idx = tid; idx < RNUM*64; idx += 128) { sRK[idx] = relk[idx]; sRV[idx] = relv[idx]; }
    cpwait<1>();   // Q arrived (K0 may still be in flight)
    __syncthreads();

    // precompute q . rel_k : [64 i][9]
    for (int idx = tid; idx < 64*RNUM; idx += 128) {
        int ii = idx / RNUM, rr = idx % RNUM;
        float s = 0.f;
        #pragma unroll 8
        for (int d = 0; d < 64; d++)
            s += __half2float(Qf[d*KQS+ii]) * sRK[rr*64 + d];
        sQRK[idx] = s;
    }
    __syncthreads();

    float accO[8][4];
    #pragma unroll
    for (int nb=0;nb<8;nb++)
        #pragma unroll
        for (int e=0;e<4;e++) accO[nb][e]=0.f;
    float mrun0=-1e30f, mrun1=-1e30f, lrun0=0.f, lrun1=0.f;

    for (int jt = 0; jt < NJT; jt++) {
        int j0t = jt*64;
        int buf = jt & 1;
        if (jt+1 < NJT){ load_kv(jt+1, buf^1); cpcommit(); }
        for (int idx = l; idx < 16*12; idx += 32) sPB[(w*16 + idx/12)*12 + (idx%12)] = 0.f;
        if (tid < 64) sMask[buf*64 + tid] = mask[(size_t)b*TT + j0t + tid];
        if (jt+1 < NJT) cpwait<1>(); else cpwait<0>();
        __syncthreads();

        const __half* Kb = Kf + buf*64*KQS;
        const __half* Vb = Vf + buf*64*KQS;
        const float* mk = sMask + buf*64;

        // ---- S = Q K^T ----
        float S[8][4];
        #pragma unroll
        for (int nb=0;nb<8;nb++)
            #pragma unroll
            for (int e=0;e<4;e++) S[nb][e]=0.f;
        #pragma unroll
        for (int ks=0; ks<4; ks++){
            int d0 = ks*16;
            unsigned Af[4];
            {
                int row = d0 + ((l>>4)&1)*8 + (l&7);
                int col = w*16 + ((l>>3)&1)*8;
                ldsm4t(Af, &Qf[row*KQS + col]);
            }
            #pragma unroll
            for (int nbp=0; nbp<4; nbp++){
                unsigned Bf[4];
                int row = d0 + ((l>>3)&1)*8 + (l&7);
                int col = nbp*16 + ((l>>4)&1)*8;
                ldsm4t(Bf, &Kb[row*KQS + col]);
                mma16816(S[2*nbp],   Af, &Bf[0]);
                mma16816(S[2*nbp+1], Af, &Bf[2]);
            }
        }

        // ---- rel-k band + mask ----
        #pragma unroll
        for (int nb=0;nb<8;nb++){
            #pragma unroll
            for (int e=0;e<4;e++){
                int iloc = w*16 + r + ((e&2)?8:0);
                int jloc = nb*8 + c2 + (e&1);
                int delta = (j0t + jloc) - (i0 + iloc);
                if (delta >= -WW && delta <= WW) S[nb][e] += sQRK[iloc*RNUM + delta + WW];
                if (mk[jloc] == 0.f) S[nb][e] = -1e30f;
            }
        }

        // ---- online softmax ----
        float tm0 = -1e30f, tm1 = -1e30f;
        #pragma unroll
        for (int nb=0;nb<8;nb++){
            tm0 = fmaxf(tm0, fmaxf(S[nb][0], S[nb][1]));
            tm1 = fmaxf(tm1, fmaxf(S[nb][2], S[nb][3]));
        }
        tm0 = fmaxf(tm0, __shfl_xor_sync(0xffffffffu, tm0, 1));
        tm0 = fmaxf(tm0, __shfl_xor_sync(0xffffffffu, tm0, 2));
        tm1 = fmaxf(tm1, __shfl_xor_sync(0xffffffffu, tm1, 1));
        tm1 = fmaxf(tm1, __shfl_xor_sync(0xffffffffu, tm1, 2));
        float mn0 = fmaxf(mrun0, tm0), mn1 = fmaxf(mrun1, tm1);
        float co0 = __expf(mrun0 - mn0), co1 = __expf(mrun1 - mn1);
        float rs0 = 0.f, rs1 = 0.f;
        #pragma unroll
        for (int nb=0;nb<8;nb++){
            S[nb][0] = __expf(S[nb][0]-mn0); rs0 += S[nb][0];
            S[nb][1] = __expf(S[nb][1]-mn0); rs0 += S[nb][1];
            S[nb][2] = __expf(S[nb][2]-mn1); rs1 += S[nb][2];
            S[nb][3] = __expf(S[nb][3]-mn1); rs1 += S[nb][3];
        }
        rs0 += __shfl_xor_sync(0xffffffffu, rs0, 1);
        rs0 += __shfl_xor_sync(0xffffffffu, rs0, 2);
        rs1 += __shfl_xor_sync(0xffffffffu, rs1, 1);
        rs1 += __shfl_xor_sync(0xffffffffu, rs1, 2);
        lrun0 = lrun0*co0 + rs0; mrun0 = mn0;
        lrun1 = lrun1*co1 + rs1; mrun1 = mn1;
        #pragma unroll
        for (int nb=0;nb<8;nb++){
            accO[nb][0]*=co0; accO[nb][1]*=co0;
            accO[nb][2]*=co1; accO[nb][3]*=co1;
        }

        // ---- band P -> sPB ----
        #pragma unroll
        for (int nb=0;nb<8;nb++){
            #pragma unroll
            for (int e=0;e<4;e++){
                int iloc = w*16 + r + ((e&2)?8:0);
                int jloc = nb*8 + c2 + (e&1);
                int delta = (j0t + jloc) - (i0 + iloc);
                if (delta >= -WW && delta <= WW) sPB[iloc*12 + delta + WW] = S[nb][e];
            }
        }
        __syncwarp();

        // ---- O += P V ----
        #pragma unroll
        for (int s=0; s<4; s++){
            unsigned Pf[4];
            Pf[0] = pack_h2(S[2*s][0],   S[2*s][1]);
            Pf[1] = pack_h2(S[2*s][2],   S[2*s][3]);
            Pf[2] = pack_h2(S[2*s+1][0], S[2*s+1][1]);
            Pf[3] = pack_h2(S[2*s+1][2], S[2*s+1][3]);
            #pragma unroll
            for (int dp=0; dp<4; dp++){
                unsigned Bf[4];
                int row = dp*16 + ((l>>4)&1)*8 + (l&7);
                int col = s*16 + ((l>>3)&1)*8;
                ldsm4(Bf, &Vb[row*KQS + col]);
                mma16816(accO[2*dp],   Pf, &Bf[0]);
                mma16816(accO[2*dp+1], Pf, &Bf[2]);
            }
        }

        // ---- O += P_band * rel_v ----
        {
            int r0i = (w*16 + r)*12, r1i = (w*16 + r + 8)*12;
            #pragma unroll
            for (int t=0; t<RNUM; t++){
                float pb0 = sPB[r0i + t];
                float pb1 = sPB[r1i + t];
                #pragma unroll
                for (int nb=0;nb<8;nb++){
                    int d0 = nb*8 + c2;
                    float rv0 = sRV[t*64 + d0];
                    float rv1 = sRV[t*64 + d0 + 1];
                    accO[nb][0] += pb0*rv0; accO[nb][1] += pb0*rv1;
                    accO[nb][2] += pb1*rv0; accO[nb][3] += pb1*rv1;
                }
            }
        }
        __syncthreads();
    }

    // ---- normalize, stage fp32 [d][i], fp16 write ----
    float inv0 = 1.f / lrun0, inv1 = 1.f / lrun1;
    #pragma unroll
    for (int nb=0;nb<8;nb++){
        #pragma unroll
        for (int e=0;e<4;e++){
            int iloc = w*16 + r + ((e&2)?8:0);
            int d = nb*8 + c2 + (e&1);
            sO[d*68 + iloc] = accO[nb][e] * ((e&2)?inv1:inv0);
        }
    }
    __syncthreads();
    #pragma unroll
    for (int p=0;p<4;p++){
        int c = tid + p*128;
        int row = c>>3, col8 = (c&7)*8;
        size_t go = hbo + (size_t)row*TT + i0 + col8;
        #pragma unroll
        for (int j=0;j<8;j+=2){
            float v0 = sO[row*68 + col8 + j];
            float v1 = sO[row*68 + col8 + j + 1];
            *(__half2*)&of[go + j] = __floats2half2_rn(v0, v1);
        }
    }
}

// ---------------- fused residual + LayerNorm; writes fp32 + fp16(masked) ----
__global__ void __launch_bounds__(256) add_ln_kernel(
    const float* __restrict__ res, const float* __restrict__ y,
    const float* __restrict__ g, const float* __restrict__ beta,
    const float* __restrict__ mask, int mask_f32, float* __restrict__ dst,
    __half* __restrict__ dstH)
{
    __shared__ float sS[8][32], sS2[8][32];
    int b  = blockIdx.y;
    int tt = threadIdx.x & 31;
    int cg = threadIdx.x >> 5;
    int t  = blockIdx.x*32 + tt;
    size_t base = (size_t)b*CC*TT + t;
    float s=0.f, s2=0.f;
    for (int c=cg; c<CC; c+=8){
        float vv = res[base + (size_t)c*TT] + y[base + (size_t)c*TT];
        s += vv; s2 += vv*vv;
    }
    sS[cg][tt]=s; sS2[cg][tt]=s2;
    __syncthreads();
    if (cg==0){
        #pragma unroll
        for (int i=1;i<8;i++){ s += sS[i][tt]; s2 += sS2[i][tt]; }
        float mean = s * (1.f/CC);
        float var  = s2 * (1.f/CC) - mean*mean;
        sS[0][tt]  = mean;
        sS2[0][tt] = rsqrtf(var + 1e-6f);
    }
    __syncthreads();
    float mean = sS[0][tt], inv = sS2[0][tt];
    float mk = mask[(size_t)b*TT + t];
    float mkf = mask_f32 ? mk : 1.f;
    for (int c=cg; c<CC; c+=8){
        float vv  = res[base + (size_t)c*TT] + y[base + (size_t)c*TT];
        float ovv = (vv-mean)*inv*g[c] + beta[c];
        dst[base + (size_t)c*TT] = ovv*mkf;
        dstH[base + (size_t)c*TT] = __float2half(ovv*mk);
    }
}

#define ATTN_SMEM_BYTES 56576

extern "C" void kernel_launch(void* const* d_in, const int* in_sizes, int n_in,
                              void* d_out, int out_size)
{
    const float* x    = (const float*)d_in[0];
    const float* mask = (const float*)d_in[1];
    const float* qw   = (const float*)d_in[2];
    const float* qb   = (const float*)d_in[3];
    const float* kw   = (const float*)d_in[4];
    const float* kb   = (const float*)d_in[5];
    const float* vw   = (const float*)d_in[6];
    const float* vb   = (const float*)d_in[7];
    const float* ow   = (const float*)d_in[8];
    const float* ob   = (const float*)d_in[9];
    const float* rk   = (const float*)d_in[10];
    const float* rv   = (const float*)d_in[11];
    const float* ln1g = (const float*)d_in[12];
    const float* ln1b = (const float*)d_in[13];
    const float* w1   = (const float*)d_in[14];
    const float* b1   = (const float*)d_in[15];
    const float* w2   = (const float*)d_in[16];
    const float* b2   = (const float*)d_in[17];
    const float* ln2g = (const float*)d_in[18];
    const float* ln2b = (const float*)d_in[19];

    float *gx,*gt,*bqkv;
    __half *gxf,*gqkv,*gof,*ghf;
    __half *wqkv,*wo,*w1f,*w2f;
    cudaGetSymbolAddress((void**)&gx, g_x);
    cudaGetSymbolAddress((void**)&gt, g_t);
    cudaGetSymbolAddress((void**)&gxf, g_xf);
    cudaGetSymbolAddress((void**)&gqkv, g_qkv);
    cudaGetSymbolAddress((void**)&gof, g_of);
    cudaGetSymbolAddress((void**)&ghf, g_hf);
    cudaGetSymbolAddress((void**)&wqkv, g_wqkv);
    cudaGetSymbolAddress((void**)&bqkv, g_bqkv);
    cudaGetSymbolAddress((void**)&wo, g_wo);
    cudaGetSymbolAddress((void**)&w1f, g_w1);
    cudaGetSymbolAddress((void**)&w2f, g_w2);

    cudaFuncSetAttribute(attn_mma_kernel, cudaFuncAttributeMaxDynamicSharedMemorySize, ATTN_SMEM_BYTES);
    cudaFuncSetAttribute(gemm_f16_kernel<0,0,1,1>, cudaFuncAttributeMaxDynamicSharedMemorySize, GEMM_SMEM_BYTES);
    cudaFuncSetAttribute(gemm_f16_kernel<0,0,0,0>, cudaFuncAttributeMaxDynamicSharedMemorySize, GEMM_SMEM_BYTES);
    cudaFuncSetAttribute(gemm_f16_kernel<1,1,1,0>, cudaFuncAttributeMaxDynamicSharedMemorySize, GEMM_SMEM_BYTES);
    cudaFuncSetAttribute(gemm_f16_kernel<0,1,0,0>, cudaFuncAttributeMaxDynamicSharedMemorySize, GEMM_SMEM_BYTES);

    // prologue: convert input + weights once
    {
        int nx = BB*CC*TT;
        cvt_copy_kernel<<<nx/4/256, 256>>>(x, gx, gxf, nx);
        cvt3_kernel<<<(LL*3*CC*CC)/4/256, 256>>>(qw, kw, vw, wqkv);
        cat_bias_kernel<<<(LL*3*CC + 255)/256, 256>>>(qb, kb, vb, bqkv);
        int ntot = NW_O + 2*NW_F;
        cvt_w_kernel<<<ntot/4/256, 256>>>(ow, w1, w2, wo, w1f, w2f);
    }

    const float inv_scale = 0.125f; // 1/sqrt(64)
    dim3 blk(256);
    for (int i=0;i<LL;i++){
        size_t wofs = (size_t)i*CC*CC;
        size_t fofs = (size_t)i*FF*CC;
        // fused q|k|v projection -> fp16 [b][3C][T]; rows<CC (=q) scaled
        gemm_f16_kernel<0,0,1,1><<<dim3(TT/128, 3*CC/128, BB), blk, GEMM_SMEM_BYTES>>>(
            wqkv + (size_t)i*3*CC*CC, gxf, bqkv + i*3*CC, mask, nullptr, gqkv,
            3*CC, TT, CC, inv_scale, CC);
        // attention -> fp16 o
        attn_mma_kernel<<<dim3(TT/64, HH, BB), dim3(128), ATTN_SMEM_BYTES>>>(
            gqkv, rk + (size_t)i*RNUM*HDD, rv + (size_t)i*RNUM*HDD, mask, gof);
        // o projection -> fp32
        gemm_f16_kernel<0,0,0,0><<<dim3(TT/128, CC/128, BB), blk, GEMM_SMEM_BYTES>>>(
            wo+wofs, gof, ob+i*CC, mask, gt, nullptr, CC, TT, CC, 1.f, 0);
        // ln1: fp32 unmasked residual, fp16 masked (feeds w1)
        add_ln_kernel<<<dim3(TT/32, BB), blk>>>(gx, gt, ln1g+i*CC, ln1b+i*CC, mask, 0, gx, gxf);
        // ffn
        gemm_f16_kernel<1,1,1,0><<<dim3(TT/128, FF/128, BB), blk, GEMM_SMEM_BYTES>>>(
            w1f+fofs, gxf, b1+i*FF, mask, nullptr, ghf, FF, TT, CC, 1.f, 0);
        gemm_f16_kernel<0,1,0,0><<<dim3(TT/128, CC/128, BB), blk, GEMM_SMEM_BYTES>>>(
            w2f+fofs, ghf, b2+i*CC, mask, gt, nullptr, CC, TT, FF, 1.f, 0);
        // ln2: fp32 masked (residual/next-layer/final), fp16 masked (feeds next q/k/v)
        float* dst = (i==LL-1) ? (float*)d_out : gx;
        add_ln_kernel<<<dim3(TT/32, BB), blk>>>(gx, gt, ln2g+i*CC, ln2b+i*CC, mask, 1, dst, gxf);
    }
}

// round 16
// speedup vs baseline: 1.0174x; 1.0174x over previous
#include <cuda_runtime.h>
#include <cuda_fp16.h>
#include <math.h>

#define BB 4
#define CC 512
#define TT 1024
#define HH 8
#define HDD 64
#define FF 2048
#define LL 4
#define WW 4
#define RNUM 9

// ---------------- scratch (no allocations allowed) ----------------
__device__ float g_x[BB*CC*TT];          // fp32 residual / layer state
__device__ float g_t[BB*CC*TT];          // fp32 gemm output (pre-LN)
// fp16 activations
__device__ __half g_xf[BB*CC*TT];
__device__ __half g_qkv[BB*3*CC*TT];     // fused q|k|v per batch
__device__ __half g_of[BB*CC*TT];
__device__ __half g_hf[BB*FF*TT];
// fp16 weights
__device__ __half g_wqkv[LL*3*CC*CC];    // [L][q|k|v][CC][CC]
__device__ float  g_bqkv[LL*3*CC];
__device__ __half g_wo[LL*CC*CC];
__device__ __half g_w1[LL*FF*CC], g_w2[LL*CC*FF];

// ---------------- helpers ----------------
__device__ __forceinline__ void mma16816(float* d, const unsigned* a, const unsigned* b){
    asm volatile("mma.sync.aligned.m16n8k16.row.col.f32.f16.f16.f32 "
        "{%0,%1,%2,%3}, {%4,%5,%6,%7}, {%8,%9}, {%0,%1,%2,%3};"
        : "+f"(d[0]),"+f"(d[1]),"+f"(d[2]),"+f"(d[3])
        : "r"(a[0]),"r"(a[1]),"r"(a[2]),"r"(a[3]), "r"(b[0]),"r"(b[1]));
}
__device__ __forceinline__ void ldsm4(unsigned* r, const void* p){
    unsigned addr = (unsigned)__cvta_generic_to_shared(p);
    asm volatile("ldmatrix.sync.aligned.m8n8.x4.shared.b16 {%0,%1,%2,%3}, [%4];"
        : "=r"(r[0]),"=r"(r[1]),"=r"(r[2]),"=r"(r[3]) : "r"(addr));
}
__device__ __forceinline__ void ldsm4t(unsigned* r, const void* p){
    unsigned addr = (unsigned)__cvta_generic_to_shared(p);
    asm volatile("ldmatrix.sync.aligned.m8n8.x4.trans.shared.b16 {%0,%1,%2,%3}, [%4];"
        : "=r"(r[0]),"=r"(r[1]),"=r"(r[2]),"=r"(r[3]) : "r"(addr));
}
__device__ __forceinline__ unsigned pack_h2(float x, float y){
    __half2 t = __floats2half2_rn(x, y);
    return *(unsigned*)&t;
}
__device__ __forceinline__ void cpa16(void* s, const void* g){
    unsigned sa = (unsigned)__cvta_generic_to_shared(s);
    asm volatile("cp.async.cg.shared.global [%0], [%1], 16;" :: "r"(sa), "l"(g));
}
__device__ __forceinline__ void cpcommit(){ asm volatile("cp.async.commit_group;"); }
template<int NN> __device__ __forceinline__ void cpwait(){ asm volatile("cp.async.wait_group %0;" :: "n"(NN)); }

// ---------------- prologue converts ----------------
__global__ void cvt_kernel(const float* __restrict__ in, __half* __restrict__ o, int n){
    int i = (blockIdx.x*blockDim.x + threadIdx.x)*4;
    if (i >= n) return;
    float4 v = *(const float4*)&in[i];
    *(__half2*)&o[i]   = __floats2half2_rn(v.x, v.y);
    *(__half2*)&o[i+2] = __floats2half2_rn(v.z, v.w);
}
// interleave q,k,v weights -> [L][3][CC][CC]
__global__ void cvt3_kernel(const float* __restrict__ q, const float* __restrict__ k,
                            const float* __restrict__ v, __half* __restrict__ dst){
    const int per = CC*CC;
    int i = (blockIdx.x*blockDim.x + threadIdx.x)*4;
    if (i >= LL*3*per) return;
    int layer = i/(3*per); int rem = i - layer*3*per; int sel = rem/per; int off = rem - sel*per;
    const float* s = sel==0 ? q : (sel==1 ? k : v);
    float4 vv = *(const float4*)&s[layer*per + off];
    *(__half2*)&dst[i]   = __floats2half2_rn(vv.x, vv.y);
    *(__half2*)&dst[i+2] = __floats2half2_rn(vv.z, vv.w);
}
__global__ void cat_bias_kernel(const float* __restrict__ qb, const float* __restrict__ kb,
                                const float* __restrict__ vb, float* __restrict__ dst){
    int i = blockIdx.x*blockDim.x + threadIdx.x;
    if (i >= LL*3*CC) return;
    int layer = i/(3*CC); int rem = i - layer*3*CC; int sel = rem/CC; int off = rem - sel*CC;
    const float* s = sel==0 ? qb : (sel==1 ? kb : vb);
    dst[i] = s[layer*CC + off];
}
// fused convert of ow, w1, w2
#define NW_O  (LL*CC*CC)
#define NW_F  (LL*FF*CC)
__global__ void cvt_w_kernel(const float* __restrict__ ow, const float* __restrict__ w1,
                             const float* __restrict__ w2,
                             __half* __restrict__ dow, __half* __restrict__ dw1,
                             __half* __restrict__ dw2){
    int i = (blockIdx.x*blockDim.x + threadIdx.x)*4;
    const float* s; __half* d; int off;
    if (i < NW_O){ s = ow; d = dow; off = i; }
    else if (i < NW_O + NW_F){ s = w1; d = dw1; off = i - NW_O; }
    else if (i < NW_O + 2*NW_F){ s = w2; d = dw2; off = i - NW_O - NW_F; }
    else return;
    float4 v = *(const float4*)&s[off];
    *(__half2*)&d[off]   = __floats2half2_rn(v.x, v.y);
    *(__half2*)&d[off+2] = __floats2half2_rn(v.z, v.w);
}

// ---------------- fp16 GEMM, 64-k double-buffered cp.async stages ----------------
// out[b][m][n] = sum_k A[m][k] B[b][k][n] (+bias, epilogue). rows<scaleM get *scale.
#define GA_ELEMS (128*72)
#define GB_ELEMS (64*136)
#define GEMM_SMEM_BYTES (2*(GA_ELEMS + GB_ELEMS)*2)
template<int RELU, int MASK_OUT, int F16_OUT, int DO_SCALE>
__global__ void __launch_bounds__(256,2) gemm_f16_kernel(
    const __half* __restrict__ A_g, const __half* __restrict__ B_g,
    const float* __restrict__ bias, const float* __restrict__ mask,
    float* __restrict__ outF, __half* __restrict__ outH,
    int M, int N, int K, float scale, int scaleM)
{
    extern __shared__ char gsm[];
    __half* Asm = (__half*)gsm;                       // [2][128][72]
    __half* Bsm = (__half*)gsm + 2*GA_ELEMS;          // [2][64][136]

    int b = blockIdx.z;
    const __half* B_b = B_g + (size_t)b*K*N;
    int m0 = blockIdx.y*128, n0 = blockIdx.x*128;
    int tid = threadIdx.x;
    int l = tid & 31, w = tid >> 5;
    int wm0 = (w >> 2) * 64;
    int wn0 = (w & 3) * 32;

    float acc[4][4][4];
    #pragma unroll
    for (int mi=0;mi<4;mi++)
        #pragma unroll
        for (int ni=0;ni<4;ni++)
            #pragma unroll
            for (int e=0;e<4;e++) acc[mi][ni][e]=0.f;

    int nt = K/64;
    auto load_stage = [&](int it, int buf){
        int k0 = it*64;
        __half* As = Asm + buf*GA_ELEMS;
        __half* Bs = Bsm + buf*GB_ELEMS;
        #pragma unroll
        for (int p=0;p<4;p++){
            int c = tid + p*256;
            int row = c>>3, col8 = (c&7)*8;
            cpa16(&As[row*72 + col8], A_g + (size_t)(m0+row)*K + k0 + col8);
        }
        #pragma unroll
        for (int p=0;p<4;p++){
            int c = tid + p*256;
            int row = c>>4, col8 = (c&15)*8;
            cpa16(&Bs[row*136 + col8], B_b + (size_t)(k0+row)*N + n0 + col8);
        }
    };

    load_stage(0,0); cpcommit();
    if (nt > 1){ load_stage(1,1); cpcommit(); }

    for (int it=0; it<nt; ++it){
        int buf = it & 1;
        if (it+1 < nt) cpwait<1>(); else cpwait<0>();
        __syncthreads();

        const __half* As = Asm + buf*GA_ELEMS;
        const __half* Bs = Bsm + buf*GB_ELEMS;

        #pragma unroll
        for (int ks=0; ks<64; ks+=16){
            unsigned Bq[2][4];
            #pragma unroll
            for (int nip=0;nip<2;nip++){
                int row = ks + ((l>>3)&1)*8 + (l&7);
                int col = wn0 + nip*16 + ((l>>4)&1)*8;
                ldsm4t(Bq[nip], &Bs[row*136 + col]);
            }
            #pragma unroll
            for (int mi=0;mi<4;mi++){
                unsigned Af[4];
                ldsm4(Af, &As[(wm0 + mi*16 + (l & 15))*72 + ks + (l >> 4)*8]);
                #pragma unroll
                for (int nip=0;nip<2;nip++){
                    mma16816(acc[mi][2*nip],   Af, &Bq[nip][0]);
                    mma16816(acc[mi][2*nip+1], Af, &Bq[nip][2]);
                }
            }
        }
        __syncthreads();
        if (it+2 < nt){ load_stage(it+2, buf); cpcommit(); }
    }

    // epilogue
    float tsc = (DO_SCALE && m0 < scaleM) ? scale : 1.f;
    #pragma unroll
    for (int mi=0;mi<4;mi++){
        int r = m0 + wm0 + mi*16 + (l >> 2);
        float bv0 = bias[r], bv1 = bias[r+8];
        #pragma unroll
        for (int ni=0;ni<4;ni++){
            int cn = n0 + wn0 + ni*8 + (l & 3)*2;
            float m00=1.f, m01=1.f;
            if (MASK_OUT){
                m00 = mask[(size_t)b*TT + cn];
                m01 = mask[(size_t)b*TT + cn + 1];
            }
            float c0 = acc[mi][ni][0] + bv0;
            float c1 = acc[mi][ni][1] + bv0;
            float c2 = acc[mi][ni][2] + bv1;
            float c3 = acc[mi][ni][3] + bv1;
            if (DO_SCALE){ c0*=tsc; c1*=tsc; c2*=tsc; c3*=tsc; }
            if (RELU){ c0=fmaxf(c0,0.f); c1=fmaxf(c1,0.f); c2=fmaxf(c2,0.f); c3=fmaxf(c3,0.f); }
            if (MASK_OUT){ c0*=m00; c1*=m01; c2*=m00; c3*=m01; }
            size_t base = (size_t)b*M*N;
            if (F16_OUT){
                *(__half2*)&outH[base + (size_t)r*N + cn]     = __floats2half2_rn(c0,c1);
                *(__half2*)&outH[base + (size_t)(r+8)*N + cn] = __floats2half2_rn(c2,c3);
            } else {
                *(float2*)&outF[base + (size_t)r*N + cn]     = make_float2(c0,c1);
                *(float2*)&outF[base + (size_t)(r+8)*N + cn] = make_float2(c2,c3);
            }
        }
    }
}

// ---------------- tensor-core flash attention, fp16, double-buffered K/V ----------------
// grid (T/64, H, B), 128 threads (4 warps). qkv fused [b][3C][T]; o fp16 [b][C][T].
#define KQS 72
#define NJT (TT/64)
__global__ void __launch_bounds__(128) attn_mma_kernel(
    const __half* __restrict__ qkv,
    const float* __restrict__ relk, const float* __restrict__ relv,
    const float* __restrict__ mask, __half* __restrict__ of)
{
    extern __shared__ char smraw[];
    __half* Qf = (__half*)smraw;                      // [64 d][72]
    __half* Kf = Qf + 64*KQS;                         // [2][64 d][72]
    __half* Vf = Kf + 2*64*KQS;                       // [2][64 d][72]
    float* sQRK  = (float*)(Vf + 2*64*KQS);           // [64 i][9]
    float* sRK   = sQRK + 64*RNUM;                    // [9][64]
    float* sRV   = sRK + RNUM*64;                     // [9][64]
    float* sPB   = sRV + RNUM*64;                     // [64 i][12]
    float* sMask = sPB + 64*12;                       // [2][64]
    float* sO    = (float*)Kf;                        // [64 d][68] fp32 out stage (overlays K)

    int tid = threadIdx.x;
    int l = tid & 31, w = tid >> 5;
    int r = l >> 2;
    int c2 = (l & 3) * 2;
    int i0 = blockIdx.x * 64;
    int h  = blockIdx.y;
    int b  = blockIdx.z;
    const size_t hbq = ((size_t)b*3*CC + h*HDD) * TT;
    const size_t hbk = hbq + (size_t)CC*TT;
    const size_t hbv = hbq + (size_t)2*CC*TT;
    const size_t hbo = ((size_t)b*CC + h*HDD) * TT;

    auto load_kv = [&](int jt, int buf){
        int j0t = jt*64;
        #pragma unroll
        for (int p=0;p<4;p++){
            int c = tid + p*128;
            int row = c>>3, col8 = (c&7)*8;
            size_t go = (size_t)row*TT + j0t + col8;
            cpa16(&Kf[buf*64*KQS + row*KQS + col8], qkv + hbk + go);
            cpa16(&Vf[buf*64*KQS + row*KQS + col8], qkv + hbv + go);
        }
    };

    // Q tile
    #pragma unroll
    for (int p=0;p<4;p++){
        int c = tid + p*128;
        int row = c>>3, col8 = (c&7)*8;
        cpa16(&Qf[row*KQS + col8], qkv + hbq + (size_t)row*TT + i0 + col8);
    }
    cpcommit();
    load_kv(0,0); cpcommit();
    for (int idx = tid; idx < RNUM*64; idx += 128) { sRK[idx] = relk[idx]; sRV[idx] = relv[idx]; }
    cpwait<1>();   // Q arrived (K0 may still be in flight)
    __syncthreads();

    // precompute q . rel_k : [64 i][9]
    for (int idx = tid; idx < 64*RNUM; idx += 128) {
        int ii = idx / RNUM, rr = idx % RNUM;
        float s = 0.f;
        #pragma unroll 8
        for (int d = 0; d < 64; d++)
            s += __half2float(Qf[d*KQS+ii]) * sRK[rr*64 + d];
        sQRK[idx] = s;
    }
    __syncthreads();

    float accO[8][4];
    #pragma unroll
    for (int nb=0;nb<8;nb++)
        #pragma unroll
        for (int e=0;e<4;e++) accO[nb][e]=0.f;
    float mrun0=-1e30f, mrun1=-1e30f, lrun0=0.f, lrun1=0.f;

    for (int jt = 0; jt < NJT; jt++) {
        int j0t = jt*64;
        int buf = jt & 1;
        if (jt+1 < NJT){ load_kv(jt+1, buf^1); cpcommit(); }
        for (int idx = l; idx < 16*12; idx += 32) sPB[(w*16 + idx/12)*12 + (idx%12)] = 0.f;
        if (tid < 64) sMask[buf*64 + tid] = mask[(size_t)b*TT + j0t + tid];
        if (jt+1 < NJT) cpwait<1>(); else cpwait<0>();
        __syncthreads();

        const __half* Kb = Kf + buf*64*KQS;
        const __half* Vb = Vf + buf*64*KQS;
        const float* mk = sMask + buf*64;

        // ---- S = Q K^T ----
        float S[8][4];
        #pragma unroll
        for (int nb=0;nb<8;nb++)
            #pragma unroll
            for (int e=0;e<4;e++) S[nb][e]=0.f;
        #pragma unroll
        for (int ks=0; ks<4; ks++){
            int d0 = ks*16;
            unsigned Af[4];
            {
                int row = d0 + ((l>>4)&1)*8 + (l&7);
                int col = w*16 + ((l>>3)&1)*8;
                ldsm4t(Af, &Qf[row*KQS + col]);
            }
            #pragma unroll
            for (int nbp=0; nbp<4; nbp++){
                unsigned Bf[4];
                int row = d0 + ((l>>3)&1)*8 + (l&7);
                int col = nbp*16 + ((l>>4)&1)*8;
                ldsm4t(Bf, &Kb[row*KQS + col]);
                mma16816(S[2*nbp],   Af, &Bf[0]);
                mma16816(S[2*nbp+1], Af, &Bf[2]);
            }
        }

        // ---- rel-k band + mask ----
        #pragma unroll
        for (int nb=0;nb<8;nb++){
            #pragma unroll
            for (int e=0;e<4;e++){
                int iloc = w*16 + r + ((e&2)?8:0);
                int jloc = nb*8 + c2 + (e&1);
                int delta = (j0t + jloc) - (i0 + iloc);
                if (delta >= -WW && delta <= WW) S[nb][e] += sQRK[iloc*RNUM + delta + WW];
                if (mk[jloc] == 0.f) S[nb][e] = -1e30f;
            }
        }

        // ---- online softmax ----
        float tm0 = -1e30f, tm1 = -1e30f;
        #pragma unroll
        for (int nb=0;nb<8;nb++){
            tm0 = fmaxf(tm0, fmaxf(S[nb][0], S[nb][1]));
            tm1 = fmaxf(tm1, fmaxf(S[nb][2], S[nb][3]));
        }
        tm0 = fmaxf(tm0, __shfl_xor_sync(0xffffffffu, tm0, 1));
        tm0 = fmaxf(tm0, __shfl_xor_sync(0xffffffffu, tm0, 2));
        tm1 = fmaxf(tm1, __shfl_xor_sync(0xffffffffu, tm1, 1));
        tm1 = fmaxf(tm1, __shfl_xor_sync(0xffffffffu, tm1, 2));
        float mn0 = fmaxf(mrun0, tm0), mn1 = fmaxf(mrun1, tm1);
        float co0 = __expf(mrun0 - mn0), co1 = __expf(mrun1 - mn1);
        float rs0 = 0.f, rs1 = 0.f;
        #pragma unroll
        for (int nb=0;nb<8;nb++){
            S[nb][0] = __expf(S[nb][0]-mn0); rs0 += S[nb][0];
            S[nb][1] = __expf(S[nb][1]-mn0); rs0 += S[nb][1];
            S[nb][2] = __expf(S[nb][2]-mn1); rs1 += S[nb][2];
            S[nb][3] = __expf(S[nb][3]-mn1); rs1 += S[nb][3];
        }
        rs0 += __shfl_xor_sync(0xffffffffu, rs0, 1);
        rs0 += __shfl_xor_sync(0xffffffffu, rs0, 2);
        rs1 += __shfl_xor_sync(0xffffffffu, rs1, 1);
        rs1 += __shfl_xor_sync(0xffffffffu, rs1, 2);
        lrun0 = lrun0*co0 + rs0; mrun0 = mn0;
        lrun1 = lrun1*co1 + rs1; mrun1 = mn1;
        #pragma unroll
        for (int nb=0;nb<8;nb++){
            accO[nb][0]*=co0; accO[nb][1]*=co0;
            accO[nb][2]*=co1; accO[nb][3]*=co1;
        }

        // ---- band P -> sPB ----
        #pragma unroll
        for (int nb=0;nb<8;nb++){
            #pragma unroll
            for (int e=0;e<4;e++){
                int iloc = w*16 + r + ((e&2)?8:0);
                int jloc = nb*8 + c2 + (e&1);
                int delta = (j0t + jloc) - (i0 + iloc);
                if (delta >= -WW && delta <= WW) sPB[iloc*12 + delta + WW] = S[nb][e];
            }
        }
        __syncwarp();

        // ---- O += P V ----
        #pragma unroll
        for (int s=0; s<4; s++){
            unsigned Pf[4];
            Pf[0] = pack_h2(S[2*s][0],   S[2*s][1]);
            Pf[1] = pack_h2(S[2*s][2],   S[2*s][3]);
            Pf[2] = pack_h2(S[2*s+1][0], S[2*s+1][1]);
            Pf[3] = pack_h2(S[2*s+1][2], S[2*s+1][3]);
            #pragma unroll
            for (int dp=0; dp<4; dp++){
                unsigned Bf[4];
                int row = dp*16 + ((l>>4)&1)*8 + (l&7);
                int col = s*16 + ((l>>3)&1)*8;
                ldsm4(Bf, &Vb[row*KQS + col]);
                mma16816(accO[2*dp],   Pf, &Bf[0]);
                mma16816(accO[2*dp+1], Pf, &Bf[2]);
            }
        }

        // ---- O += P_band * rel_v ----
        {
            int r0i = (w*16 + r)*12, r1i = (w*16 + r + 8)*12;
            #pragma unroll
            for (int t=0; t<RNUM; t++){
                float pb0 = sPB[r0i + t];
                float pb1 = sPB[r1i + t];
                #pragma unroll
                for (int nb=0;nb<8;nb++){
                    int d0 = nb*8 + c2;
                    float rv0 = sRV[t*64 + d0];
                    float rv1 = sRV[t*64 + d0 + 1];
                    accO[nb][0] += pb0*rv0; accO[nb][1] += pb0*rv1;
                    accO[nb][2] += pb1*rv0; accO[nb][3] += pb1*rv1;
                }
            }
        }
        __syncthreads();
    }

    // ---- normalize, stage fp32 [d][i], fp16 write ----
    float inv0 = 1.f / lrun0, inv1 = 1.f / lrun1;
    #pragma unroll
    for (int nb=0;nb<8;nb++){
        #pragma unroll
        for (int e=0;e<4;e++){
            int iloc = w*16 + r + ((e&2)?8:0);
            int d = nb*8 + c2 + (e&1);
            sO[d*68 + iloc] = accO[nb][e] * ((e&2)?inv1:inv0);
        }
    }
    __syncthreads();
    #pragma unroll
    for (int p=0;p<4;p++){
        int c = tid + p*128;
        int row = c>>3, col8 = (c&7)*8;
        size_t go = hbo + (size_t)row*TT + i0 + col8;
        #pragma unroll
        for (int j=0;j<8;j+=2){
            float v0 = sO[row*68 + col8 + j];
            float v1 = sO[row*68 + col8 + j + 1];
            *(__half2*)&of[go + j] = __floats2half2_rn(v0, v1);
        }
    }
}

// ---------------- fused residual + LayerNorm; writes fp32 + fp16(masked) ----
__global__ void __launch_bounds__(256) add_ln_kernel(
    const float* __restrict__ res, const float* __restrict__ y,
    const float* __restrict__ g, const float* __restrict__ beta,
    const float* __restrict__ mask, int mask_f32, float* __restrict__ dst,
    __half* __restrict__ dstH)
{
    __shared__ float sS[8][32], sS2[8][32];
    int b  = blockIdx.y;
    int tt = threadIdx.x & 31;
    int cg = threadIdx.x >> 5;
    int t  = blockIdx.x*32 + tt;
    size_t base = (size_t)b*CC*TT + t;
    float s=0.f, s2=0.f;
    for (int c=cg; c<CC; c+=8){
        float vv = res[base + (size_t)c*TT] + y[base + (size_t)c*TT];
        s += vv; s2 += vv*vv;
    }
    sS[cg][tt]=s; sS2[cg][tt]=s2;
    __syncthreads();
    if (cg==0){
        #pragma unroll
        for (int i=1;i<8;i++){ s += sS[i][tt]; s2 += sS2[i][tt]; }
        float mean = s * (1.f/CC);
        float var  = s2 * (1.f/CC) - mean*mean;
        sS[0][tt]  = mean;
        sS2[0][tt] = rsqrtf(var + 1e-6f);
    }
    __syncthreads();
    float mean = sS[0][tt], inv = sS2[0][tt];
    float mk = mask[(size_t)b*TT + t];
    float mkf = mask_f32 ? mk : 1.f;
    for (int c=cg; c<CC; c+=8){
        float vv  = res[base + (size_t)c*TT] + y[base + (size_t)c*TT];
        float ovv = (vv-mean)*inv*g[c] + beta[c];
        dst[base + (size_t)c*TT] = ovv*mkf;
        dstH[base + (size_t)c*TT] = __float2half(ovv*mk);
    }
}

#define ATTN_SMEM_BYTES 57344

extern "C" void kernel_launch(void* const* d_in, const int* in_sizes, int n_in,
                              void* d_out, int out_size)
{
    const float* x    = (const float*)d_in[0];
    const float* mask = (const float*)d_in[1];
    const float* qw   = (const float*)d_in[2];
    const float* qb   = (const float*)d_in[3];
    const float* kw   = (const float*)d_in[4];
    const float* kb   = (const float*)d_in[5];
    const float* vw   = (const float*)d_in[6];
    const float* vb   = (const float*)d_in[7];
    const float* ow   = (const float*)d_in[8];
    const float* ob   = (const float*)d_in[9];
    const float* rk   = (const float*)d_in[10];
    const float* rv   = (const float*)d_in[11];
    const float* ln1g = (const float*)d_in[12];
    const float* ln1b = (const float*)d_in[13];
    const float* w1   = (const float*)d_in[14];
    const float* b1   = (const float*)d_in[15];
    const float* w2   = (const float*)d_in[16];
    const float* b2   = (const float*)d_in[17];
    const float* ln2g = (const float*)d_in[18];
    const float* ln2b = (const float*)d_in[19];

    float *gx,*gt,*bqkv;
    __half *gxf,*gqkv,*gof,*ghf;
    __half *wqkv,*wo,*w1f,*w2f;
    cudaGetSymbolAddress((void**)&gx, g_x);
    cudaGetSymbolAddress((void**)&gt, g_t);
    cudaGetSymbolAddress((void**)&gxf, g_xf);
    cudaGetSymbolAddress((void**)&gqkv, g_qkv);
    cudaGetSymbolAddress((void**)&gof, g_of);
    cudaGetSymbolAddress((void**)&ghf, g_hf);
    cudaGetSymbolAddress((void**)&wqkv, g_wqkv);
    cudaGetSymbolAddress((void**)&bqkv, g_bqkv);
    cudaGetSymbolAddress((void**)&wo, g_wo);
    cudaGetSymbolAddress((void**)&w1f, g_w1);
    cudaGetSymbolAddress((void**)&w2f, g_w2);

    cudaFuncSetAttribute(attn_mma_kernel, cudaFuncAttributeMaxDynamicSharedMemorySize, ATTN_SMEM_BYTES);
    cudaFuncSetAttribute(gemm_f16_kernel<0,0,1,1>, cudaFuncAttributeMaxDynamicSharedMemorySize, GEMM_SMEM_BYTES);
    cudaFuncSetAttribute(gemm_f16_kernel<0,0,0,0>, cudaFuncAttributeMaxDynamicSharedMemorySize, GEMM_SMEM_BYTES);
    cudaFuncSetAttribute(gemm_f16_kernel<1,1,1,0>, cudaFuncAttributeMaxDynamicSharedMemorySize, GEMM_SMEM_BYTES);
    cudaFuncSetAttribute(gemm_f16_kernel<0,1,0,0>, cudaFuncAttributeMaxDynamicSharedMemorySize, GEMM_SMEM_BYTES);

    // prologue: convert input + weights once (x stays in place as layer-0 residual)
    {
        int nx = BB*CC*TT;
        cvt_kernel<<<nx/4/256, 256>>>(x, gxf, nx);
        cvt3_kernel<<<(LL*3*CC*CC)/4/256, 256>>>(qw, kw, vw, wqkv);
        cat_bias_kernel<<<(LL*3*CC + 255)/256, 256>>>(qb, kb, vb, bqkv);
        int ntot = NW_O + 2*NW_F;
        cvt_w_kernel<<<ntot/4/256, 256>>>(ow, w1, w2, wo, w1f, w2f);
    }

    const float inv_scale = 0.125f; // 1/sqrt(64)
    dim3 blk(256);
    for (int i=0;i<LL;i++){
        size_t wofs = (size_t)i*CC*CC;
        size_t fofs = (size_t)i*FF*CC;
        // fused q|k|v projection -> fp16 [b][3C][T]; rows<CC (=q) scaled
        gemm_f16_kernel<0,0,1,1><<<dim3(TT/128, 3*CC/128, BB), blk, GEMM_SMEM_BYTES>>>(
            wqkv + (size_t)i*3*CC*CC, gxf, bqkv + i*3*CC, mask, nullptr, gqkv,
            3*CC, TT, CC, inv_scale, CC);
        // attention -> fp16 o
        attn_mma_kernel<<<dim3(TT/64, HH, BB), dim3(128), ATTN_SMEM_BYTES>>>(
            gqkv, rk + (size_t)i*RNUM*HDD, rv + (size_t)i*RNUM*HDD, mask, gof);
        // o projection -> fp32
        gemm_f16_kernel<0,0,0,0><<<dim3(TT/128, CC/128, BB), blk, GEMM_SMEM_BYTES>>>(
            wo+wofs, gof, ob+i*CC, mask, gt, nullptr, CC, TT, CC, 1.f, 0);
        // ln1: residual = harness input x for layer 0, g_x thereafter
        const float* res1 = (i==0) ? x : gx;
        add_ln_kernel<<<dim3(TT/32, BB), blk>>>(res1, gt, ln1g+i*CC, ln1b+i*CC, mask, 0, gx, gxf);
        // ffn
        gemm_f16_kernel<1,1,1,0><<<dim3(TT/128, FF/128, BB), blk, GEMM_SMEM_BYTES>>>(
            w1f+fofs, gxf, b1+i*FF, mask, nullptr, ghf, FF, TT, CC, 1.f, 0);
        gemm_f16_kernel<0,1,0,0><<<dim3(TT/128, CC/128, BB), blk, GEMM_SMEM_BYTES>>>(
            w2f+fofs, ghf, b2+i*CC, mask, gt, nullptr, CC, TT, FF, 1.f, 0);
        // ln2: fp32 masked (residual/next-layer/final), fp16 masked (feeds next q/k/v)
        float* dst = (i==LL-1) ? (float*)d_out : gx;
        add_ln_kernel<<<dim3(TT/32, BB), blk>>>(gx, gt, ln2g+i*CC, ln2b+i*CC, mask, 1, dst, gxf);
    }
}